// round 13
// baseline (speedup 1.0000x reference)
#include <cuda_runtime.h>
#include <cuda_fp16.h>
#include <cstdint>

// Problem constants
#define TT 256
#define BB 16
#define HH 2048
#define LL 3
#define VV 32000
#define TB (TT*BB)       // 4096
#define H4 (4*HH)        // 8192
#define NCTA 128

// ---------------------------------------------------------------------------
// Static device scratch
// ---------------------------------------------------------------------------
__device__ __half g_wih16[(size_t)LL*H4*HH];
__device__ __half g_whh16[(size_t)LL*H4*HH];
__device__ __half g_watt16[(size_t)HH*2*HH];
__device__ __half g_decw16[(size_t)VV*HH];
__device__ __half g_x16[(size_t)TB*HH];
__device__ float  g_gin[(size_t)TB*H4];
__device__ __half g_hs16[(size_t)TB*HH];
__device__ __half g_h0_16[BB*HH];
__device__ float  g_scores[(size_t)TT*BB*TT];
__device__ __half g_attn16[(size_t)TT*BB*TT];
__device__ __half g_hsT16[(size_t)BB*HH*TT];
__device__ __half g_ctx16[(size_t)TB*HH];
__device__ float  g_att32[(size_t)TB*HH];
__device__ __half g_att16[(size_t)TB*HH];
__device__ unsigned g_bar_cnt = 0;
__device__ unsigned g_bar_gen = 0;

// ---------------------------------------------------------------------------
// Helpers
// ---------------------------------------------------------------------------
__device__ __forceinline__ void cp_async16(void* sm, const void* gm) {
    unsigned saddr = (unsigned)__cvta_generic_to_shared(sm);
    asm volatile("cp.async.cg.shared.global [%0], [%1], 16;\n" :: "r"(saddr), "l"(gm));
}
__device__ __forceinline__ void cp_commit() {
    asm volatile("cp.async.commit_group;\n");
}
template<int N>
__device__ __forceinline__ void cp_wait() {
    asm volatile("cp.async.wait_group %0;\n" :: "n"(N));
}
__device__ __forceinline__ void ldsm_x4(uint32_t& r0, uint32_t& r1, uint32_t& r2, uint32_t& r3,
                                        const void* p) {
    unsigned a = (unsigned)__cvta_generic_to_shared(p);
    asm volatile("ldmatrix.sync.aligned.m8n8.x4.shared.b16 {%0,%1,%2,%3}, [%4];\n"
                 : "=r"(r0), "=r"(r1), "=r"(r2), "=r"(r3) : "r"(a));
}
__device__ __forceinline__ void mma_16816(float& d0, float& d1, float& d2, float& d3,
                                          uint32_t a0, uint32_t a1, uint32_t a2, uint32_t a3,
                                          uint32_t b0, uint32_t b1) {
    asm volatile(
        "mma.sync.aligned.m16n8k16.row.col.f32.f16.f16.f32 "
        "{%0,%1,%2,%3}, {%4,%5,%6,%7}, {%8,%9}, {%0,%1,%2,%3};\n"
        : "+f"(d0), "+f"(d1), "+f"(d2), "+f"(d3)
        : "r"(a0), "r"(a1), "r"(a2), "r"(a3), "r"(b0), "r"(b1));
}
__device__ __forceinline__ float sigmoidf_(float x) { return 1.f / (1.f + expf(-x)); }

__device__ __forceinline__ unsigned ld_cv(const unsigned* p) {
    unsigned v;
    asm volatile("ld.global.cv.u32 %0, [%1];" : "=r"(v) : "l"(p));
    return v;
}

// Grid barrier: release via atomics, poll via .cv loads.
__device__ __forceinline__ void grid_bar(unsigned* cnt, unsigned* gen) {
    __threadfence();
    __syncthreads();
    if (threadIdx.x == 0) {
        unsigned g = ld_cv(gen);
        unsigned a = atomicAdd(cnt, 1u);
        if (a == NCTA - 1) {
            atomicExch(cnt, 0u);
            __threadfence();
            atomicAdd(gen, 1u);
        } else {
            while (ld_cv(gen) == g) { __nanosleep(32); }
        }
    }
    __syncthreads();
    __threadfence();
}

// ---------------------------------------------------------------------------
// Small utility kernels
// ---------------------------------------------------------------------------
__global__ void f32_to_f16(const float* __restrict__ src, __half* __restrict__ dst, long n) {
    long i = ((long)blockIdx.x * blockDim.x + threadIdx.x) * 4;
    if (i + 3 < n) {
        float4 v = *(const float4*)(src + i);
        *(__half2*)(dst + i)     = __floats2half2_rn(v.x, v.y);
        *(__half2*)(dst + i + 2) = __floats2half2_rn(v.z, v.w);
    }
}

__global__ void embed_gather(const int* __restrict__ ids, const float* __restrict__ emb,
                             __half* __restrict__ x16) {
    int tok = blockIdx.x;
    int id  = ids[tok];
    const float4* src = (const float4*)(emb + (size_t)id * HH);
    __half* dst = x16 + (size_t)tok * HH;
    for (int i = threadIdx.x; i < HH / 4; i += blockDim.x) {
        float4 v = src[i];
        *(__half2*)(dst + i * 4)     = __floats2half2_rn(v.x, v.y);
        *(__half2*)(dst + i * 4 + 2) = __floats2half2_rn(v.z, v.w);
    }
}

// ---------------------------------------------------------------------------
// GEMM v3: C[m,n] (+=Cacc) = sum_k A[m,k]*B[n,k] (+bias) (tanh), C f32 or f16
// CTA tile 128m x 256n, BK=64, 3-stage cp.async, 8 warps of 64x64.
// ---------------------------------------------------------------------------
#define GEMM_SMEM (3 * (128 + 256) * 72 * 2)   // 165888 bytes

template<bool BIAS, bool ACCUM, bool TANH, bool OUTH>
__global__ void __launch_bounds__(256, 1) gemm_tc(
    void* __restrict__ Cout, const float* __restrict__ Cacc,
    const __half* __restrict__ A, const __half* __restrict__ B,
    const float* __restrict__ bias,
    int M, int N, int K, long lda, long ldb, long ldc,
    long bsA, long bsB, long bsC)
{
    extern __shared__ char smraw[];
    __half* sm = (__half*)smraw;
    const int SSTG = 384 * 72;

    int tid = threadIdx.x, lane = tid & 31, w = tid >> 5;
    int wm = w >> 2, wn = w & 3;
    int mtile = blockIdx.y, ntile = blockIdx.x, z = blockIdx.z;

    const __half* Ab = A + (size_t)z * bsA + (size_t)mtile * 128 * lda;
    const __half* Bb = B + (size_t)z * bsB + (size_t)ntile * 256 * ldb;

    float acc[4][8][4];
#pragma unroll
    for (int mi = 0; mi < 4; mi++)
#pragma unroll
        for (int nj = 0; nj < 8; nj++)
#pragma unroll
            for (int q = 0; q < 4; q++) acc[mi][nj][q] = 0.f;

    const int KT = K / 64;

    auto load = [&](int kt, int st) {
        __half* Asm = sm + st * SSTG;
        __half* Bsm = Asm + 128 * 72;
        const __half* Ag = Ab + (size_t)kt * 64;
        const __half* Bg = Bb + (size_t)kt * 64;
#pragma unroll
        for (int i = 0; i < 12; i++) {
            int c = tid + i * 256;
            if (c < 1024) {
                int row = c >> 3, off = (c & 7) * 8;
                cp_async16(Asm + row * 72 + off, Ag + (size_t)row * lda + off);
            } else {
                int c2 = c - 1024;
                int row = c2 >> 3, off = (c2 & 7) * 8;
                cp_async16(Bsm + row * 72 + off, Bg + (size_t)row * ldb + off);
            }
        }
        cp_commit();
    };

    load(0, 0);
    if (KT > 1) load(1, 1);

    for (int kt = 0; kt < KT; ++kt) {
        int st = kt % 3;
        if (kt + 2 < KT) { load(kt + 2, (kt + 2) % 3); cp_wait<2>(); }
        else if (kt + 1 < KT) cp_wait<1>();
        else cp_wait<0>();
        __syncthreads();

        __half* Asm = sm + st * SSTG;
        __half* Bsm = Asm + 128 * 72;
#pragma unroll
        for (int kk = 0; kk < 4; kk++) {
            int kb = kk * 16;
            uint32_t afr[4][4];
#pragma unroll
            for (int mi = 0; mi < 4; mi++) {
                const __half* p = Asm + (wm * 64 + mi * 16 + (lane & 15)) * 72
                                  + kb + ((lane >> 4) & 1) * 8;
                ldsm_x4(afr[mi][0], afr[mi][1], afr[mi][2], afr[mi][3], p);
            }
            uint32_t bfr[8][2];
            int idx = lane >> 3;
#pragma unroll
            for (int pr = 0; pr < 4; pr++) {
                const __half* p = Bsm + (wn * 64 + pr * 16 + ((idx >> 1) & 1) * 8 + (lane & 7)) * 72
                                  + kb + (idx & 1) * 8;
                ldsm_x4(bfr[2 * pr][0], bfr[2 * pr][1], bfr[2 * pr + 1][0], bfr[2 * pr + 1][1], p);
            }
#pragma unroll
            for (int mi = 0; mi < 4; mi++)
#pragma unroll
                for (int nj = 0; nj < 8; nj++)
                    mma_16816(acc[mi][nj][0], acc[mi][nj][1], acc[mi][nj][2], acc[mi][nj][3],
                              afr[mi][0], afr[mi][1], afr[mi][2], afr[mi][3],
                              bfr[nj][0], bfr[nj][1]);
        }
        __syncthreads();
    }

#pragma unroll
    for (int mi = 0; mi < 4; mi++) {
        int r0 = mtile * 128 + wm * 64 + mi * 16 + (lane >> 2);
        int r1 = r0 + 8;
#pragma unroll
        for (int nj = 0; nj < 8; nj++) {
            int col = ntile * 256 + wn * 64 + nj * 8 + (lane & 3) * 2;
            size_t i0 = (size_t)r0 * ldc + col;
            size_t i1 = (size_t)r1 * ldc + col;
            float2 v01 = make_float2(acc[mi][nj][0], acc[mi][nj][1]);
            float2 v23 = make_float2(acc[mi][nj][2], acc[mi][nj][3]);
            if (ACCUM) {
                const float* Ca = Cacc + (size_t)z * bsC;
                float2 o0 = *(const float2*)&Ca[i0];
                float2 o1 = *(const float2*)&Ca[i1];
                v01.x += o0.x; v01.y += o0.y; v23.x += o1.x; v23.y += o1.y;
            }
            if (BIAS) {
                float b0 = bias[col], b1 = bias[col + 1];
                v01.x += b0; v01.y += b1; v23.x += b0; v23.y += b1;
            }
            if (TANH) {
                v01.x = tanhf(v01.x); v01.y = tanhf(v01.y);
                v23.x = tanhf(v23.x); v23.y = tanhf(v23.y);
            }
            if (OUTH) {
                __half* Ch = (__half*)Cout + (size_t)z * bsC;
                *(__half2*)&Ch[i0] = __floats2half2_rn(v01.x, v01.y);
                *(__half2*)&Ch[i1] = __floats2half2_rn(v23.x, v23.y);
            } else {
                float* Cf = (float*)Cout + (size_t)z * bsC;
                *(float2*)&Cf[i0] = v01;
                *(float2*)&Cf[i1] = v23;
            }
        }
    }
}

// ---------------------------------------------------------------------------
// Persistent LSTM layer v7 = R9 (v4) + split-phase barrier with t-invariant
// weight prefetch in the arrive window. Layout, warp map, mainloop identical
// to the passing R9 kernel:
//   CTA blk owns 16 hidden units = 64 Whh rows; rows 0..47 (i,f,g) resident;
//   rows 48..63 (o) streamed via 3-deep ring, K-chunks of 64 (16 iters).
//   Warps: rg = w&1 owns 32 rows, kq = w>>1 owns the kq-th k16 per half.
//   Rs = [4][16][64] f32 overlays the As+Bstg rings (reads complete at the
//   cell, before any arrive-window cp.async writes ring buffers 0/1).
// Barrier split: arrive (tid0 atomicAdd; last CTA releases) -> prefetch the
// streamed-weight parts of chunks 0,1 for the next step (t-invariant, safe:
// ring bufs 0,1 past last read, guarded by mainloop-end sync) -> poll release
// -> issue A parts of chunks 0,1. Group accounting: pending at it=0 is
// [W01, A0, A1]; wait<1> completes W01 and A0 — same wait pattern as R9.
// ---------------------------------------------------------------------------
#define LSTM_SMEM 225024
// Bres [48][2056] f16 @0       (197376 B)
// As   [2q][3][16][72] @197376 (13824 B)   <- Rs f32 [4][16][64] overlays As+Bstg
// Bstg [2q][3][16][72] @211200 (13824 B)

__global__ void __launch_bounds__(256, 1) lstm_layer_persist(
    const float* __restrict__ h0,
    const float* __restrict__ c0,
    const float* __restrict__ gin,
    const __half* __restrict__ whh,
    __half* __restrict__ hs16,
    __half* __restrict__ h016,
    unsigned* bar_cnt, unsigned* bar_gen)
{
    extern __shared__ char smraw[];
    __half* Bres = (__half*)smraw;
    __half* As   = (__half*)(smraw + 197376);
    __half* Bstg = (__half*)(smraw + 211200);
    float*  Rs   = (float*)(smraw + 197376);   // overlay on As+Bstg rings

    const int tid = threadIdx.x, lane = tid & 31, w = tid >> 5;
    const int rg = w & 1, kq = w >> 1;         // rows 32*rg..32*rg+31, k16 tile kq
    const int blk = blockIdx.x;

    // resident weight rows 0..47 (gates i,f,g)
#pragma unroll
    for (int i = 0; i < 48; i++) {
        int c = tid + i * 256;
        int row = c >> 8, off = (c & 255) * 8;
        cp_async16(Bres + (size_t)row * 2056 + off,
                   whh + (size_t)((row >> 4) * HH + blk * 16 + (row & 15)) * HH + off);
    }
    cp_commit();

    // h0 conversion (grid covers exactly 16*2048)
    {
        int idx = blk * 256 + tid;
        h016[idx] = __float2half_rn(h0[idx]);
    }

    const int cr = tid >> 4, cu = tid & 15;
    const int ccol = blk * 16 + cu;
    float creg = c0[(size_t)cr * HH + ccol];

    grid_bar(bar_cnt, bar_gen);    // h016 visible everywhere; Bres in flight
    cp_wait<0>();                  // Bres resident
    __syncthreads();

    // loader indices: 1 A cp + 1 W cp per chunk per thread
    const int lq = tid >> 7;             // K half this thread loads
    const int lr = (tid >> 3) & 15;      // row
    const int lo = (tid & 7) * 8;        // 16B offset
    const __half* wsrc = whh + (size_t)(3 * HH + blk * 16 + lr) * HH + lq * 1024 + lo;

    // W-part / A-part loaders (no commit inside; caller commits)
    auto load_W = [&](int it) {
        int buf = it % 3;
        cp_async16(Bstg + ((lq * 3 + buf) * 16 + lr) * 72 + lo, wsrc + it * 64);
    };
    auto load_A = [&](const __half* hp, int it) {
        int buf = it % 3;
        cp_async16(As + ((lq * 3 + buf) * 16 + lr) * 72 + lo,
                   hp + (size_t)lr * HH + lq * 1024 + it * 64 + lo);
    };

    // prologue: W parts of chunks 0,1 for step 0 (one group)
    load_W(0); load_W(1); cp_commit();

    for (int t = 0; t < TT; ++t) {
        const __half* hp = t ? (hs16 + (size_t)(t - 1) * BB * HH) : h016;

        // prefetch gate inputs (hidden behind the MMA loop)
        const float* g0 = gin + (size_t)t * BB * H4 + (size_t)cr * H4;
        float pgi = __ldg(g0 + ccol);
        float pgf = __ldg(g0 + HH + ccol);
        float pgg = __ldg(g0 + 2 * HH + ccol);
        float pgo = __ldg(g0 + 3 * HH + ccol);

        // A parts of chunks 0,1 (separate groups to preserve wait semantics)
        load_A(hp, 0); cp_commit();
        load_A(hp, 1); cp_commit();

        float acc[4][4];      // 4 n8 tiles of this warp's 32 rows
#pragma unroll
        for (int nt = 0; nt < 4; nt++)
#pragma unroll
            for (int qq = 0; qq < 4; qq++) acc[nt][qq] = 0.f;

        for (int it = 0; it < 16; ++it) {
            int buf = it % 3;
            if (it < 15) cp_wait<1>(); else cp_wait<0>();
            __syncthreads();
            if (it < 14) {                 // combined A+W group for chunk it+2
                load_A(hp, it + 2);
                load_W(it + 2);
                cp_commit();
            }

#pragma unroll
            for (int h = 0; h < 2; h++) {
                // A: 16x16 fragment at (half h, k16 tile kq)
                uint32_t a0, a1, a2, a3;
                ldsm_x4(a0, a1, a2, a3,
                        As + ((h * 3 + buf) * 16 + (lane & 15)) * 72
                           + kq * 16 + ((lane >> 4) & 1) * 8);
                int brow = ((lane >> 4) & 1) * 8 + (lane & 7);
                int kof  = kq * 16 + ((lane >> 3) & 1) * 8;
#pragma unroll
                for (int ni2 = 0; ni2 < 2; ni2++) {
                    uint32_t b0, b1, b2, b3;
                    if (rg == 0 || ni2 == 0) {
                        // resident rows (i,f for rg0; g for rg1/ni2=0)
                        int row0 = rg * 32 + ni2 * 16;
                        ldsm_x4(b0, b1, b2, b3,
                                Bres + (size_t)(row0 + brow) * 2056
                                     + h * 1024 + it * 64 + kof);
                    } else {
                        // streamed o rows (48..63)
                        ldsm_x4(b0, b1, b2, b3,
                                Bstg + ((h * 3 + buf) * 16 + brow) * 72 + kof);
                    }
                    mma_16816(acc[ni2 * 2][0], acc[ni2 * 2][1], acc[ni2 * 2][2], acc[ni2 * 2][3],
                              a0, a1, a2, a3, b0, b1);
                    mma_16816(acc[ni2 * 2 + 1][0], acc[ni2 * 2 + 1][1],
                              acc[ni2 * 2 + 1][2], acc[ni2 * 2 + 1][3],
                              a0, a1, a2, a3, b2, b3);
                }
            }
        }
        __syncthreads();   // all buffer reads done before Rs overlay writes

        // write 4 partial sums: Rs[kq][16 batch][64 units]
        {
            int r = lane >> 2;
            int cp2 = (lane & 3) * 2;
#pragma unroll
            for (int nt = 0; nt < 4; nt++) {
                int cidx = rg * 32 + nt * 8 + cp2;
                Rs[(kq * 16 + r) * 64 + cidx]         = acc[nt][0];
                Rs[(kq * 16 + r) * 64 + cidx + 1]     = acc[nt][1];
                Rs[(kq * 16 + r + 8) * 64 + cidx]     = acc[nt][2];
                Rs[(kq * 16 + r + 8) * 64 + cidx + 1] = acc[nt][3];
            }
        }
        __syncthreads();

        // LSTM cell: sum the 4 k-partials per gate
        {
            float gi = pgi, gf = pgf, gg = pgg, go = pgo;
#pragma unroll
            for (int p = 0; p < 4; p++) {
                const float* rp = Rs + (p * 16 + cr) * 64;
                gi += rp[cu];
                gf += rp[16 + cu];
                gg += rp[32 + cu];
                go += rp[48 + cu];
            }
            creg = sigmoidf_(gf) * creg + sigmoidf_(gi) * tanhf(gg);
            float hval = sigmoidf_(go) * tanhf(creg);
            hs16[(size_t)t * BB * HH + (size_t)cr * HH + ccol] = __float2half_rn(hval);
        }

        // split-phase grid barrier with weight prefetch in the arrive window
        if (t < TT - 1) {
            __threadfence();       // h(t) stores visible before arrival
            __syncthreads();       // all threads' stores + Rs reads complete
            unsigned gsnap = 0;
            if (tid == 0) {
                gsnap = ld_cv(bar_gen);
                unsigned a = atomicAdd(bar_cnt, 1u);
                if (a == NCTA - 1) {
                    atomicExch(bar_cnt, 0u);
                    __threadfence();
                    atomicAdd(bar_gen, 1u);
                }
            }
            // arrive window: t-invariant weight prefetch for next step
            load_W(0); load_W(1); cp_commit();
            if (tid == 0) {
                while (ld_cv(bar_gen) == gsnap) { __nanosleep(32); }
            }
            __syncthreads();
            __threadfence();
        }
    }
}

// ---------------------------------------------------------------------------
// Causal softmax
// ---------------------------------------------------------------------------
__global__ void softmax_causal(const float* __restrict__ scores, __half* __restrict__ attn) {
    int row = blockIdx.x;
    int t = row >> 4;
    const float* sp = scores + (size_t)row * TT;
    __half* ap = attn + (size_t)row * TT;
    int s = threadIdx.x;
    const float inv = 0.022097086912079608f; // 1/sqrt(2048)
    float v = (s <= t) ? sp[s] * inv : -1e30f;
    __shared__ float red[256];
    red[s] = v; __syncthreads();
    for (int o = 128; o > 0; o >>= 1) { if (s < o) red[s] = fmaxf(red[s], red[s + o]); __syncthreads(); }
    float m = red[0]; __syncthreads();
    float e = (s <= t) ? expf(v - m) : 0.f;
    red[s] = e; __syncthreads();
    for (int o = 128; o > 0; o >>= 1) { if (s < o) red[s] += red[s + o]; __syncthreads(); }
    float sum = red[0];
    ap[s] = __float2half_rn(e / sum);
}

__global__ void transpose_hs(const __half* __restrict__ hs, __half* __restrict__ hsT) {
    long i = (long)blockIdx.x * blockDim.x + threadIdx.x;
    if (i >= (long)BB * HH * TT) return;
    int t = i & (TT - 1);
    long r = i >> 8;
    int h = r & (HH - 1);
    int b = (int)(r >> 11);
    hsT[i] = hs[(size_t)t * (BB * HH) + (size_t)b * HH + h];
}

// ---------------------------------------------------------------------------
// Host driver
// ---------------------------------------------------------------------------
extern "C" void kernel_launch(void* const* d_in, const int* in_sizes, int n_in,
                              void* d_out, int out_size) {
    const int*   ids  = (const int*)d_in[0];
    const float* h0   = (const float*)d_in[1];
    const float* c0   = (const float*)d_in[2];
    const float* embW = (const float*)d_in[3];
    const float* Wih  = (const float*)d_in[4];
    const float* Whh  = (const float*)d_in[5];
    const float* bvec = (const float*)d_in[6];
    const float* Watt = (const float*)d_in[7];
    const float* batt = (const float*)d_in[8];
    const float* decW = (const float*)d_in[9];
    const float* decb = (const float*)d_in[10];
    float* out = (float*)d_out;

    __half *wih16, *whh16, *watt16, *decw16, *x16, *hs16, *h016, *attn16, *hsT16, *ctx16, *att16;
    float *gin, *scores, *att32;
    unsigned *barc, *barg;
    cudaGetSymbolAddress((void**)&wih16,  g_wih16);
    cudaGetSymbolAddress((void**)&whh16,  g_whh16);
    cudaGetSymbolAddress((void**)&watt16, g_watt16);
    cudaGetSymbolAddress((void**)&decw16, g_decw16);
    cudaGetSymbolAddress((void**)&x16,    g_x16);
    cudaGetSymbolAddress((void**)&gin,    g_gin);
    cudaGetSymbolAddress((void**)&hs16,   g_hs16);
    cudaGetSymbolAddress((void**)&h016,   g_h0_16);
    cudaGetSymbolAddress((void**)&scores, g_scores);
    cudaGetSymbolAddress((void**)&attn16, g_attn16);
    cudaGetSymbolAddress((void**)&hsT16,  g_hsT16);
    cudaGetSymbolAddress((void**)&ctx16,  g_ctx16);
    cudaGetSymbolAddress((void**)&att32,  g_att32);
    cudaGetSymbolAddress((void**)&att16,  g_att16);
    cudaGetSymbolAddress((void**)&barc,   g_bar_cnt);
    cudaGetSymbolAddress((void**)&barg,   g_bar_gen);

    cudaFuncSetAttribute(gemm_tc<true,  false, false, false>, cudaFuncAttributeMaxDynamicSharedMemorySize, GEMM_SMEM);
    cudaFuncSetAttribute(gemm_tc<false, false, false, false>, cudaFuncAttributeMaxDynamicSharedMemorySize, GEMM_SMEM);
    cudaFuncSetAttribute(gemm_tc<false, false, false, true >, cudaFuncAttributeMaxDynamicSharedMemorySize, GEMM_SMEM);
    cudaFuncSetAttribute(gemm_tc<true,  true,  true,  true >, cudaFuncAttributeMaxDynamicSharedMemorySize, GEMM_SMEM);
    cudaFuncSetAttribute(lstm_layer_persist, cudaFuncAttributeMaxDynamicSharedMemorySize, LSTM_SMEM);

    const long nWih = (long)LL * H4 * HH;
    const long nWatt = (long)HH * 2 * HH;
    const long nDec = (long)VV * HH;

    f32_to_f16<<<(unsigned)(nWih / 1024), 256>>>(Wih,  wih16, nWih);
    f32_to_f16<<<(unsigned)(nWih / 1024), 256>>>(Whh,  whh16, nWih);
    f32_to_f16<<<(unsigned)(nWatt / 1024), 256>>>(Watt, watt16, nWatt);
    f32_to_f16<<<(unsigned)(nDec / 1024), 256>>>(decW, decw16, nDec);

    embed_gather<<<TB, 256>>>(ids, embW, x16);

    const long layerW = (long)H4 * HH;

    for (int l = 0; l < LL; l++) {
        const __half* xin = (l == 0) ? x16 : hs16;
        // Gin = X @ Wih_l^T + b_l : [4096, 8192], K=2048
        gemm_tc<true, false, false, false><<<dim3(H4 / 256, TB / 128, 1), 256, GEMM_SMEM>>>(
            gin, nullptr, xin, wih16 + (size_t)l * layerW, bvec + (size_t)l * H4,
            TB, H4, HH, HH, HH, H4, 0, 0, 0);
        lstm_layer_persist<<<NCTA, 256, LSTM_SMEM>>>(
            h0 + (size_t)l * BB * HH, c0 + (size_t)l * BB * HH,
            gin, whh16 + (size_t)l * layerW, hs16, h016, barc, barg);
    }

    // attention scores: per-batch [256,256] = hs @ hs^T (K=2048)
    gemm_tc<false, false, false, false><<<dim3(1, 2, BB), 256, GEMM_SMEM>>>(
        scores, nullptr, hs16, hs16, nullptr,
        TT, TT, HH, (long)BB * HH, (long)BB * HH, (long)BB * TT,
        HH, HH, TT);

    softmax_causal<<<TB, 256>>>(scores, attn16);

    transpose_hs<<<(unsigned)((long)BB * HH * TT / 256), 256>>>(hs16, hsT16);

    // ctx = attn @ hs per batch: M=256, N=2048, K=256 -> half output directly
    gemm_tc<false, false, false, true><<<dim3(HH / 256, 2, BB), 256, GEMM_SMEM>>>(
        ctx16, nullptr, attn16, hsT16, nullptr,
        TT, HH, TT, (long)BB * TT, TT, (long)BB * HH,
        TT, (long)HH * TT, HH);

    // out = tanh(hs @ W1^T + ctx @ W2^T + b_att): f32 partial, then fused f16
    gemm_tc<false, false, false, false><<<dim3(HH / 256, TB / 128, 1), 256, GEMM_SMEM>>>(
        att32, nullptr, hs16, watt16, nullptr,
        TB, HH, HH, HH, 2 * HH, HH, 0, 0, 0);
    gemm_tc<true, true, true, true><<<dim3(HH / 256, TB / 128, 1), 256, GEMM_SMEM>>>(
        att16, att32, ctx16, watt16 + HH, batt,
        TB, HH, HH, HH, 2 * HH, HH, 0, 0, 0);

    // decode: [4096, 32000], K=2048
    gemm_tc<true, false, false, false><<<dim3(VV / 256, TB / 128, 1), 256, GEMM_SMEM>>>(
        out, nullptr, att16, decw16, decb,
        TB, VV, HH, HH, HH, VV, 0, 0, 0);
}

// round 14
// speedup vs baseline: 1.5439x; 1.5439x over previous
#include <cuda_runtime.h>
#include <cuda_fp16.h>
#include <cstdint>

// Problem constants
#define TT 256
#define BB 16
#define HH 2048
#define LL 3
#define VV 32000
#define TB (TT*BB)       // 4096
#define H4 (4*HH)        // 8192
#define NCTA 128

// ---------------------------------------------------------------------------
// Static device scratch
// ---------------------------------------------------------------------------
__device__ __half g_wih16[(size_t)LL*H4*HH];
__device__ __half g_whh16[(size_t)LL*H4*HH];
__device__ __half g_watt16[(size_t)HH*2*HH];
__device__ __half g_decw16[(size_t)VV*HH];
__device__ __half g_x16[(size_t)TB*HH];
__device__ float  g_gin[(size_t)TB*H4];
__device__ __half g_hs16[(size_t)TB*HH];
__device__ __half g_h0_16[BB*HH];
__device__ float  g_scores[(size_t)TT*BB*TT];
__device__ __half g_attn16[(size_t)TT*BB*TT];
__device__ __half g_hsT16[(size_t)BB*HH*TT];
__device__ __half g_ctx16[(size_t)TB*HH];
__device__ float  g_att32[(size_t)TB*HH];
__device__ __half g_att16[(size_t)TB*HH];
__device__ unsigned g_bar_cnt = 0;
__device__ unsigned g_bar_gen = 0;

// ---------------------------------------------------------------------------
// Helpers
// ---------------------------------------------------------------------------
__device__ __forceinline__ void cp_async16(void* sm, const void* gm) {
    unsigned saddr = (unsigned)__cvta_generic_to_shared(sm);
    asm volatile("cp.async.cg.shared.global [%0], [%1], 16;\n" :: "r"(saddr), "l"(gm));
}
__device__ __forceinline__ void cp_commit() {
    asm volatile("cp.async.commit_group;\n");
}
template<int N>
__device__ __forceinline__ void cp_wait() {
    asm volatile("cp.async.wait_group %0;\n" :: "n"(N));
}
__device__ __forceinline__ void ldsm_x4(uint32_t& r0, uint32_t& r1, uint32_t& r2, uint32_t& r3,
                                        const void* p) {
    unsigned a = (unsigned)__cvta_generic_to_shared(p);
    asm volatile("ldmatrix.sync.aligned.m8n8.x4.shared.b16 {%0,%1,%2,%3}, [%4];\n"
                 : "=r"(r0), "=r"(r1), "=r"(r2), "=r"(r3) : "r"(a));
}
__device__ __forceinline__ void mma_16816(float& d0, float& d1, float& d2, float& d3,
                                          uint32_t a0, uint32_t a1, uint32_t a2, uint32_t a3,
                                          uint32_t b0, uint32_t b1) {
    asm volatile(
        "mma.sync.aligned.m16n8k16.row.col.f32.f16.f16.f32 "
        "{%0,%1,%2,%3}, {%4,%5,%6,%7}, {%8,%9}, {%0,%1,%2,%3};\n"
        : "+f"(d0), "+f"(d1), "+f"(d2), "+f"(d3)
        : "r"(a0), "r"(a1), "r"(a2), "r"(a3), "r"(b0), "r"(b1));
}
__device__ __forceinline__ float sigmoidf_(float x) { return 1.f / (1.f + expf(-x)); }

__device__ __forceinline__ unsigned ld_cv(const unsigned* p) {
    unsigned v;
    asm volatile("ld.global.cv.u32 %0, [%1];" : "=r"(v) : "l"(p));
    return v;
}

// Grid barrier: release via atomics, poll via .cv loads.
__device__ __forceinline__ void grid_bar(unsigned* cnt, unsigned* gen) {
    __threadfence();
    __syncthreads();
    if (threadIdx.x == 0) {
        unsigned g = ld_cv(gen);
        unsigned a = atomicAdd(cnt, 1u);
        if (a == NCTA - 1) {
            atomicExch(cnt, 0u);
            __threadfence();
            atomicAdd(gen, 1u);
        } else {
            while (ld_cv(gen) == g) { __nanosleep(32); }
        }
    }
    __syncthreads();
    __threadfence();
}

// ---------------------------------------------------------------------------
// Small utility kernels
// ---------------------------------------------------------------------------
__global__ void f32_to_f16(const float* __restrict__ src, __half* __restrict__ dst, long n) {
    long i = ((long)blockIdx.x * blockDim.x + threadIdx.x) * 4;
    if (i + 3 < n) {
        float4 v = *(const float4*)(src + i);
        *(__half2*)(dst + i)     = __floats2half2_rn(v.x, v.y);
        *(__half2*)(dst + i + 2) = __floats2half2_rn(v.z, v.w);
    }
}

__global__ void embed_gather(const int* __restrict__ ids, const float* __restrict__ emb,
                             __half* __restrict__ x16) {
    int tok = blockIdx.x;
    int id  = ids[tok];
    const float4* src = (const float4*)(emb + (size_t)id * HH);
    __half* dst = x16 + (size_t)tok * HH;
    for (int i = threadIdx.x; i < HH / 4; i += blockDim.x) {
        float4 v = src[i];
        *(__half2*)(dst + i * 4)     = __floats2half2_rn(v.x, v.y);
        *(__half2*)(dst + i * 4 + 2) = __floats2half2_rn(v.z, v.w);
    }
}

// ---------------------------------------------------------------------------
// GEMM v3: C[m,n] (+=Cacc) = sum_k A[m,k]*B[n,k] (+bias) (tanh), C f32 or f16
// CTA tile 128m x 256n, BK=64, 3-stage cp.async, 8 warps of 64x64.
// ---------------------------------------------------------------------------
#define GEMM_SMEM (3 * (128 + 256) * 72 * 2)   // 165888 bytes

template<bool BIAS, bool ACCUM, bool TANH, bool OUTH>
__global__ void __launch_bounds__(256, 1) gemm_tc(
    void* __restrict__ Cout, const float* __restrict__ Cacc,
    const __half* __restrict__ A, const __half* __restrict__ B,
    const float* __restrict__ bias,
    int M, int N, int K, long lda, long ldb, long ldc,
    long bsA, long bsB, long bsC)
{
    extern __shared__ char smraw[];
    __half* sm = (__half*)smraw;
    const int SSTG = 384 * 72;

    int tid = threadIdx.x, lane = tid & 31, w = tid >> 5;
    int wm = w >> 2, wn = w & 3;
    int mtile = blockIdx.y, ntile = blockIdx.x, z = blockIdx.z;

    const __half* Ab = A + (size_t)z * bsA + (size_t)mtile * 128 * lda;
    const __half* Bb = B + (size_t)z * bsB + (size_t)ntile * 256 * ldb;

    float acc[4][8][4];
#pragma unroll
    for (int mi = 0; mi < 4; mi++)
#pragma unroll
        for (int nj = 0; nj < 8; nj++)
#pragma unroll
            for (int q = 0; q < 4; q++) acc[mi][nj][q] = 0.f;

    const int KT = K / 64;

    auto load = [&](int kt, int st) {
        __half* Asm = sm + st * SSTG;
        __half* Bsm = Asm + 128 * 72;
        const __half* Ag = Ab + (size_t)kt * 64;
        const __half* Bg = Bb + (size_t)kt * 64;
#pragma unroll
        for (int i = 0; i < 12; i++) {
            int c = tid + i * 256;
            if (c < 1024) {
                int row = c >> 3, off = (c & 7) * 8;
                cp_async16(Asm + row * 72 + off, Ag + (size_t)row * lda + off);
            } else {
                int c2 = c - 1024;
                int row = c2 >> 3, off = (c2 & 7) * 8;
                cp_async16(Bsm + row * 72 + off, Bg + (size_t)row * ldb + off);
            }
        }
        cp_commit();
    };

    load(0, 0);
    if (KT > 1) load(1, 1);

    for (int kt = 0; kt < KT; ++kt) {
        int st = kt % 3;
        if (kt + 2 < KT) { load(kt + 2, (kt + 2) % 3); cp_wait<2>(); }
        else if (kt + 1 < KT) cp_wait<1>();
        else cp_wait<0>();
        __syncthreads();

        __half* Asm = sm + st * SSTG;
        __half* Bsm = Asm + 128 * 72;
#pragma unroll
        for (int kk = 0; kk < 4; kk++) {
            int kb = kk * 16;
            uint32_t afr[4][4];
#pragma unroll
            for (int mi = 0; mi < 4; mi++) {
                const __half* p = Asm + (wm * 64 + mi * 16 + (lane & 15)) * 72
                                  + kb + ((lane >> 4) & 1) * 8;
                ldsm_x4(afr[mi][0], afr[mi][1], afr[mi][2], afr[mi][3], p);
            }
            uint32_t bfr[8][2];
            int idx = lane >> 3;
#pragma unroll
            for (int pr = 0; pr < 4; pr++) {
                const __half* p = Bsm + (wn * 64 + pr * 16 + ((idx >> 1) & 1) * 8 + (lane & 7)) * 72
                                  + kb + (idx & 1) * 8;
                ldsm_x4(bfr[2 * pr][0], bfr[2 * pr][1], bfr[2 * pr + 1][0], bfr[2 * pr + 1][1], p);
            }
#pragma unroll
            for (int mi = 0; mi < 4; mi++)
#pragma unroll
                for (int nj = 0; nj < 8; nj++)
                    mma_16816(acc[mi][nj][0], acc[mi][nj][1], acc[mi][nj][2], acc[mi][nj][3],
                              afr[mi][0], afr[mi][1], afr[mi][2], afr[mi][3],
                              bfr[nj][0], bfr[nj][1]);
        }
        __syncthreads();
    }

#pragma unroll
    for (int mi = 0; mi < 4; mi++) {
        int r0 = mtile * 128 + wm * 64 + mi * 16 + (lane >> 2);
        int r1 = r0 + 8;
#pragma unroll
        for (int nj = 0; nj < 8; nj++) {
            int col = ntile * 256 + wn * 64 + nj * 8 + (lane & 3) * 2;
            size_t i0 = (size_t)r0 * ldc + col;
            size_t i1 = (size_t)r1 * ldc + col;
            float2 v01 = make_float2(acc[mi][nj][0], acc[mi][nj][1]);
            float2 v23 = make_float2(acc[mi][nj][2], acc[mi][nj][3]);
            if (ACCUM) {
                const float* Ca = Cacc + (size_t)z * bsC;
                float2 o0 = *(const float2*)&Ca[i0];
                float2 o1 = *(const float2*)&Ca[i1];
                v01.x += o0.x; v01.y += o0.y; v23.x += o1.x; v23.y += o1.y;
            }
            if (BIAS) {
                float b0 = bias[col], b1 = bias[col + 1];
                v01.x += b0; v01.y += b1; v23.x += b0; v23.y += b1;
            }
            if (TANH) {
                v01.x = tanhf(v01.x); v01.y = tanhf(v01.y);
                v23.x = tanhf(v23.x); v23.y = tanhf(v23.y);
            }
            if (OUTH) {
                __half* Ch = (__half*)Cout + (size_t)z * bsC;
                *(__half2*)&Ch[i0] = __floats2half2_rn(v01.x, v01.y);
                *(__half2*)&Ch[i1] = __floats2half2_rn(v23.x, v23.y);
            } else {
                float* Cf = (float*)Cout + (size_t)z * bsC;
                *(float2*)&Cf[i0] = v01;
                *(float2*)&Cf[i1] = v23;
            }
        }
    }
}

// ---------------------------------------------------------------------------
// Persistent LSTM layer v8 = EXACT R9 (9336us) structure — same layout, warp
// map, loaders, ring, Rs overlay, per-step grid barrier — with ONE change:
// all 6 LDSMs of a chunk (2 A-frags + 4 B-frags) are issued before the 8
// MMAs, so LDS latencies overlap instead of serializing per-fragment.
// ---------------------------------------------------------------------------
#define LSTM_SMEM 225024
// Bres [48][2056] f16 @0       (197376 B)
// As   [2q][3][16][72] @197376 (13824 B)   <- Rs f32 [4][16][64] overlays As+Bstg
// Bstg [2q][3][16][72] @211200 (13824 B)

__global__ void __launch_bounds__(256, 1) lstm_layer_persist(
    const float* __restrict__ h0,
    const float* __restrict__ c0,
    const float* __restrict__ gin,
    const __half* __restrict__ whh,
    __half* __restrict__ hs16,
    __half* __restrict__ h016,
    unsigned* bar_cnt, unsigned* bar_gen)
{
    extern __shared__ char smraw[];
    __half* Bres = (__half*)smraw;
    __half* As   = (__half*)(smraw + 197376);
    __half* Bstg = (__half*)(smraw + 211200);
    float*  Rs   = (float*)(smraw + 197376);   // overlay on As+Bstg rings

    const int tid = threadIdx.x, lane = tid & 31, w = tid >> 5;
    const int rg = w & 1, kq = w >> 1;         // rows 32*rg..32*rg+31, k16 tile kq
    const int blk = blockIdx.x;

    // resident weight rows 0..47 (gates i,f,g)
#pragma unroll
    for (int i = 0; i < 48; i++) {
        int c = tid + i * 256;
        int row = c >> 8, off = (c & 255) * 8;
        cp_async16(Bres + (size_t)row * 2056 + off,
                   whh + (size_t)((row >> 4) * HH + blk * 16 + (row & 15)) * HH + off);
    }
    cp_commit();

    // h0 conversion (grid covers exactly 16*2048)
    {
        int idx = blk * 256 + tid;
        h016[idx] = __float2half_rn(h0[idx]);
    }

    const int cr = tid >> 4, cu = tid & 15;
    const int ccol = blk * 16 + cu;
    float creg = c0[(size_t)cr * HH + ccol];

    grid_bar(bar_cnt, bar_gen);
    cp_wait<0>();
    __syncthreads();

    // loader indices: 1 As cp + 1 Bstg cp per chunk
    const int lq = tid >> 7;             // K half this thread loads
    const int lr = (tid >> 3) & 15;      // row
    const int lo = (tid & 7) * 8;        // 16B offset
    const __half* wsrc = whh + (size_t)(3 * HH + blk * 16 + lr) * HH + lq * 1024 + lo;

    for (int t = 0; t < TT; ++t) {
        const __half* hp = t ? (hs16 + (size_t)(t - 1) * BB * HH) : h016;

        // prefetch gate inputs (hidden behind the MMA loop)
        const float* g0 = gin + (size_t)t * BB * H4 + (size_t)cr * H4;
        float pgi = __ldg(g0 + ccol);
        float pgf = __ldg(g0 + HH + ccol);
        float pgg = __ldg(g0 + 2 * HH + ccol);
        float pgo = __ldg(g0 + 3 * HH + ccol);

        auto load_chunk = [&](int it) {
            int buf = it % 3;
            cp_async16(As + ((lq * 3 + buf) * 16 + lr) * 72 + lo,
                       hp + (size_t)lr * HH + lq * 1024 + it * 64 + lo);
            cp_async16(Bstg + ((lq * 3 + buf) * 16 + lr) * 72 + lo, wsrc + it * 64);
            cp_commit();
        };

        float acc[4][4];      // 4 n8 tiles of this warp's 32 rows
#pragma unroll
        for (int nt = 0; nt < 4; nt++)
#pragma unroll
            for (int qq = 0; qq < 4; qq++) acc[nt][qq] = 0.f;

        load_chunk(0);
        load_chunk(1);
        for (int it = 0; it < 16; ++it) {
            int buf = it % 3;
            if (it < 15) cp_wait<1>(); else cp_wait<0>();
            __syncthreads();
            if (it < 14) load_chunk(it + 2);   // buffer (it+2)%3 last read at it-1: safe

            // --- hoisted fragment loads: all 6 LDSMs before any MMA ---
            const int brow = ((lane >> 4) & 1) * 8 + (lane & 7);
            const int kof  = kq * 16 + ((lane >> 3) & 1) * 8;
            uint32_t Af[2][4];
            uint32_t Bf[2][2][4];
#pragma unroll
            for (int h = 0; h < 2; h++) {
                ldsm_x4(Af[h][0], Af[h][1], Af[h][2], Af[h][3],
                        As + ((h * 3 + buf) * 16 + (lane & 15)) * 72
                           + kq * 16 + ((lane >> 4) & 1) * 8);
            }
#pragma unroll
            for (int h = 0; h < 2; h++) {
#pragma unroll
                for (int ni2 = 0; ni2 < 2; ni2++) {
                    if (rg == 0 || ni2 == 0) {
                        int row0 = rg * 32 + ni2 * 16;
                        ldsm_x4(Bf[h][ni2][0], Bf[h][ni2][1], Bf[h][ni2][2], Bf[h][ni2][3],
                                Bres + (size_t)(row0 + brow) * 2056
                                     + h * 1024 + it * 64 + kof);
                    } else {
                        ldsm_x4(Bf[h][ni2][0], Bf[h][ni2][1], Bf[h][ni2][2], Bf[h][ni2][3],
                                Bstg + ((h * 3 + buf) * 16 + brow) * 72 + kof);
                    }
                }
            }
            // --- 8 MMAs ---
#pragma unroll
            for (int h = 0; h < 2; h++) {
#pragma unroll
                for (int ni2 = 0; ni2 < 2; ni2++) {
                    mma_16816(acc[ni2 * 2][0], acc[ni2 * 2][1], acc[ni2 * 2][2], acc[ni2 * 2][3],
                              Af[h][0], Af[h][1], Af[h][2], Af[h][3],
                              Bf[h][ni2][0], Bf[h][ni2][1]);
                    mma_16816(acc[ni2 * 2 + 1][0], acc[ni2 * 2 + 1][1],
                              acc[ni2 * 2 + 1][2], acc[ni2 * 2 + 1][3],
                              Af[h][0], Af[h][1], Af[h][2], Af[h][3],
                              Bf[h][ni2][2], Bf[h][ni2][3]);
                }
            }
        }
        __syncthreads();   // all buffer reads done before Rs overlay writes

        // write 4 partial sums: Rs[kq][16 batch][64 units]
        {
            int r = lane >> 2;
            int cp2 = (lane & 3) * 2;
#pragma unroll
            for (int nt = 0; nt < 4; nt++) {
                int cidx = rg * 32 + nt * 8 + cp2;
                Rs[(kq * 16 + r) * 64 + cidx]         = acc[nt][0];
                Rs[(kq * 16 + r) * 64 + cidx + 1]     = acc[nt][1];
                Rs[(kq * 16 + r + 8) * 64 + cidx]     = acc[nt][2];
                Rs[(kq * 16 + r + 8) * 64 + cidx + 1] = acc[nt][3];
            }
        }
        __syncthreads();

        // LSTM cell: sum the 4 k-partials per gate
        {
            float gi = pgi, gf = pgf, gg = pgg, go = pgo;
#pragma unroll
            for (int p = 0; p < 4; p++) {
                const float* rp = Rs + (p * 16 + cr) * 64;
                gi += rp[cu];
                gf += rp[16 + cu];
                gg += rp[32 + cu];
                go += rp[48 + cu];
            }
            creg = sigmoidf_(gf) * creg + sigmoidf_(gi) * tanhf(gg);
            float hval = sigmoidf_(go) * tanhf(creg);
            hs16[(size_t)t * BB * HH + (size_t)cr * HH + ccol] = __float2half_rn(hval);
        }

        grid_bar(bar_cnt, bar_gen);   // h(t) visible; also guards Rs overlay
    }
}

// ---------------------------------------------------------------------------
// Causal softmax
// ---------------------------------------------------------------------------
__global__ void softmax_causal(const float* __restrict__ scores, __half* __restrict__ attn) {
    int row = blockIdx.x;
    int t = row >> 4;
    const float* sp = scores + (size_t)row * TT;
    __half* ap = attn + (size_t)row * TT;
    int s = threadIdx.x;
    const float inv = 0.022097086912079608f; // 1/sqrt(2048)
    float v = (s <= t) ? sp[s] * inv : -1e30f;
    __shared__ float red[256];
    red[s] = v; __syncthreads();
    for (int o = 128; o > 0; o >>= 1) { if (s < o) red[s] = fmaxf(red[s], red[s + o]); __syncthreads(); }
    float m = red[0]; __syncthreads();
    float e = (s <= t) ? expf(v - m) : 0.f;
    red[s] = e; __syncthreads();
    for (int o = 128; o > 0; o >>= 1) { if (s < o) red[s] += red[s + o]; __syncthreads(); }
    float sum = red[0];
    ap[s] = __float2half_rn(e / sum);
}

// Tiled transpose hs[t][b][h] -> hsT[b][h][t]; 32x32 tiles via padded SMEM.
// grid (HH/32, TT/32, BB), block (32, 8).
__global__ void transpose_hs(const __half* __restrict__ hs, __half* __restrict__ hsT) {
    __shared__ __half tile[32][34];
    int h0 = blockIdx.x * 32;
    int t0 = blockIdx.y * 32;
    int b  = blockIdx.z;
    int tx = threadIdx.x, ty = threadIdx.y;
#pragma unroll
    for (int j = 0; j < 4; j++) {
        int tl = ty + j * 8;
        tile[tl][tx] = hs[(size_t)(t0 + tl) * (BB * HH) + (size_t)b * HH + h0 + tx];
    }
    __syncthreads();
#pragma unroll
    for (int j = 0; j < 4; j++) {
        int hl = ty + j * 8;
        hsT[(size_t)b * HH * TT + (size_t)(h0 + hl) * TT + t0 + tx] = tile[tx][hl];
    }
}

// ---------------------------------------------------------------------------
// Host driver
// ---------------------------------------------------------------------------
extern "C" void kernel_launch(void* const* d_in, const int* in_sizes, int n_in,
                              void* d_out, int out_size) {
    const int*   ids  = (const int*)d_in[0];
    const float* h0   = (const float*)d_in[1];
    const float* c0   = (const float*)d_in[2];
    const float* embW = (const float*)d_in[3];
    const float* Wih  = (const float*)d_in[4];
    const float* Whh  = (const float*)d_in[5];
    const float* bvec = (const float*)d_in[6];
    const float* Watt = (const float*)d_in[7];
    const float* batt = (const float*)d_in[8];
    const float* decW = (const float*)d_in[9];
    const float* decb = (const float*)d_in[10];
    float* out = (float*)d_out;

    __half *wih16, *whh16, *watt16, *decw16, *x16, *hs16, *h016, *attn16, *hsT16, *ctx16, *att16;
    float *gin, *scores, *att32;
    unsigned *barc, *barg;
    cudaGetSymbolAddress((void**)&wih16,  g_wih16);
    cudaGetSymbolAddress((void**)&whh16,  g_whh16);
    cudaGetSymbolAddress((void**)&watt16, g_watt16);
    cudaGetSymbolAddress((void**)&decw16, g_decw16);
    cudaGetSymbolAddress((void**)&x16,    g_x16);
    cudaGetSymbolAddress((void**)&gin,    g_gin);
    cudaGetSymbolAddress((void**)&hs16,   g_hs16);
    cudaGetSymbolAddress((void**)&h016,   g_h0_16);
    cudaGetSymbolAddress((void**)&scores, g_scores);
    cudaGetSymbolAddress((void**)&attn16, g_attn16);
    cudaGetSymbolAddress((void**)&hsT16,  g_hsT16);
    cudaGetSymbolAddress((void**)&ctx16,  g_ctx16);
    cudaGetSymbolAddress((void**)&att32,  g_att32);
    cudaGetSymbolAddress((void**)&att16,  g_att16);
    cudaGetSymbolAddress((void**)&barc,   g_bar_cnt);
    cudaGetSymbolAddress((void**)&barg,   g_bar_gen);

    cudaFuncSetAttribute(gemm_tc<true,  false, false, false>, cudaFuncAttributeMaxDynamicSharedMemorySize, GEMM_SMEM);
    cudaFuncSetAttribute(gemm_tc<false, false, false, false>, cudaFuncAttributeMaxDynamicSharedMemorySize, GEMM_SMEM);
    cudaFuncSetAttribute(gemm_tc<false, false, false, true >, cudaFuncAttributeMaxDynamicSharedMemorySize, GEMM_SMEM);
    cudaFuncSetAttribute(gemm_tc<true,  true,  true,  true >, cudaFuncAttributeMaxDynamicSharedMemorySize, GEMM_SMEM);
    cudaFuncSetAttribute(lstm_layer_persist, cudaFuncAttributeMaxDynamicSharedMemorySize, LSTM_SMEM);

    const long nWih = (long)LL * H4 * HH;
    const long nWatt = (long)HH * 2 * HH;
    const long nDec = (long)VV * HH;

    f32_to_f16<<<(unsigned)(nWih / 1024), 256>>>(Wih,  wih16, nWih);
    f32_to_f16<<<(unsigned)(nWih / 1024), 256>>>(Whh,  whh16, nWih);
    f32_to_f16<<<(unsigned)(nWatt / 1024), 256>>>(Watt, watt16, nWatt);
    f32_to_f16<<<(unsigned)(nDec / 1024), 256>>>(decW, decw16, nDec);

    embed_gather<<<TB, 256>>>(ids, embW, x16);

    const long layerW = (long)H4 * HH;

    for (int l = 0; l < LL; l++) {
        const __half* xin = (l == 0) ? x16 : hs16;
        // Gin = X @ Wih_l^T + b_l : [4096, 8192], K=2048
        gemm_tc<true, false, false, false><<<dim3(H4 / 256, TB / 128, 1), 256, GEMM_SMEM>>>(
            gin, nullptr, xin, wih16 + (size_t)l * layerW, bvec + (size_t)l * H4,
            TB, H4, HH, HH, HH, H4, 0, 0, 0);
        lstm_layer_persist<<<NCTA, 256, LSTM_SMEM>>>(
            h0 + (size_t)l * BB * HH, c0 + (size_t)l * BB * HH,
            gin, whh16 + (size_t)l * layerW, hs16, h016, barc, barg);
    }

    // attention scores: per-batch [256,256] = hs @ hs^T (K=2048)
    gemm_tc<false, false, false, false><<<dim3(1, 2, BB), 256, GEMM_SMEM>>>(
        scores, nullptr, hs16, hs16, nullptr,
        TT, TT, HH, (long)BB * HH, (long)BB * HH, (long)BB * TT,
        HH, HH, TT);

    softmax_causal<<<TB, 256>>>(scores, attn16);

    transpose_hs<<<dim3(HH / 32, TT / 32, BB), dim3(32, 8)>>>(hs16, hsT16);

    // ctx = attn @ hs per batch: M=256, N=2048, K=256 -> half output directly
    gemm_tc<false, false, false, true><<<dim3(HH / 256, 2, BB), 256, GEMM_SMEM>>>(
        ctx16, nullptr, attn16, hsT16, nullptr,
        TT, HH, TT, (long)BB * TT, TT, (long)BB * HH,
        TT, (long)HH * TT, HH);

    // out = tanh(hs @ W1^T + ctx @ W2^T + b_att): f32 partial, then fused f16
    gemm_tc<false, false, false, false><<<dim3(HH / 256, TB / 128, 1), 256, GEMM_SMEM>>>(
        att32, nullptr, hs16, watt16, nullptr,
        TB, HH, HH, HH, 2 * HH, HH, 0, 0, 0);
    gemm_tc<true, true, true, true><<<dim3(HH / 256, TB / 128, 1), 256, GEMM_SMEM>>>(
        att16, att32, ctx16, watt16 + HH, batt,
        TB, HH, HH, HH, 2 * HH, HH, 0, 0, 0);

    // decode: [4096, 32000], K=2048
    gemm_tc<true, false, false, false><<<dim3(VV / 256, TB / 128, 1), 256, GEMM_SMEM>>>(
        out, nullptr, att16, decw16, decb,
        TB, VV, HH, HH, HH, VV, 0, 0, 0);
}